// round 8
// baseline (speedup 1.0000x reference)
#include <cuda_runtime.h>

// ---------------- problem constants ----------------
#define NPTS   524288
#define TILE   128
#define NTILES (NPTS / TILE)     // 4096
#define TPB    512
#define NCTA   148
#define PADP   132
#define PBP    68                // partial-buffer point stride (floats)

#define DH   64
#define EMB  32
#define DIRD 27
#define FEAT 15
#define LAT  128
#define RGBK (EMB + DIRD + FEAT) // 74

// ---------------- smem layout (float offsets) ----------------
#define S_OCCW0 0
#define S_OCCW1 (S_OCCW0 + 32*64)
#define S_OCCW2 (S_OCCW1 + 64*64)
#define S_RGBW0 (S_OCCW2 + 64*16)
#define S_RGBW1 (S_RGBW0 + 74*64)
#define S_RGBW2 (S_RGBW1 + 64*64)
#define S_OCCB0 (S_RGBW2 + 64*3)
#define S_OCCB1 (S_OCCB0 + 64)
#define S_OCCB2 (S_OCCB1 + 64)
#define S_RGBB1 (S_OCCB2 + 16)
#define S_RGBB2 (S_RGBB1 + 64)
#define S_LATB  (S_RGBB2 + 4)
#define S_OCCV  (S_LATB + 64)
#define S_XB    (S_OCCV + 128)      // [74][PADP]
#define S_HB    (S_XB + 74*PADP)
#define S_GB    (S_HB + 64*PADP)
#define S_PB    (S_GB + 64*PADP)    // partial buffer [128][PBP]
#define S_TOTAL (S_PB + 128*PBP)    // 51964 floats = 207856 B

typedef unsigned long long u64t;

#define FMA_F32X2(d, a, b, c) \
    asm("fma.rn.f32x2 %0, %1, %2, %3;" : "=l"(d) : "l"(a), "l"(b), "l"(c))
#define ADD_F32X2(d, a, b) \
    asm("add.rn.f32x2 %0, %1, %2;" : "=l"(d) : "l"(a), "l"(b))
#define PACK_SPLAT(out, x) \
    asm("mov.b64 %0, {%1, %1};" : "=l"(out) : "r"(__float_as_uint(x)))
#define UNPACK_F32X2U(lo, hi, in) \
    asm("mov.b64 {%0, %1}, %2;" : "=r"(lo), "=r"(hi) : "l"(in))

__device__ __forceinline__ float sp_fast(float x) {
    float e = __expf(x);
    float y = __logf(1.0f + e);
    return (x > 20.0f) ? x : y;
}
__device__ __forceinline__ float sigmoid_fast(float x) {
    return 1.0f / (1.0f + __expf(-x));
}

// K-split dense layer: Y[128 x 64] = act(X[128 x K] @ W + b)
// Group 0 (threads 0-255): k in [0, KHALF), finalizes neurons 8tx..8tx+3.
// Group 1 (threads 256-511): k in [K-KHALF, K), finalizes neurons 8tx+4..8tx+7.
// Thread tile: 4 points x 8 neurons (f32x2 neuron pairs). Two __syncthreads inside.
template<int K, bool ACT>
__device__ __forceinline__ void layer64_ks(float* sm, int xoff, int woff,
                                           int boff, int yoff, int tg, int group)
{
    constexpr int KHALF = (K + 1) / 2;
    const int k0 = group ? (K - KHALF) : 0;
    const int ty = tg >> 3;
    const int tx = tg & 7;
    const float* xp = sm + xoff + 4 * ty + k0 * PADP;
    const float* wp = sm + woff + 8 * tx + k0 * 64;

    u64t acc[4][4];
    #pragma unroll
    for (int p = 0; p < 4; p++) {
        #pragma unroll
        for (int q = 0; q < 4; q++) acc[p][q] = 0ULL;
    }

    #pragma unroll 8
    for (int i = 0; i < KHALF; i++) {
        float4 xv = *(const float4*)(xp + i * PADP);
        u64t xs0, xs1, xs2, xs3;
        PACK_SPLAT(xs0, xv.x); PACK_SPLAT(xs1, xv.y);
        PACK_SPLAT(xs2, xv.z); PACK_SPLAT(xs3, xv.w);
        ulonglong2 wA = *(const ulonglong2*)(wp + i * 64);
        ulonglong2 wB = *(const ulonglong2*)(wp + i * 64 + 4);
        FMA_F32X2(acc[0][0], xs0, wA.x, acc[0][0]);
        FMA_F32X2(acc[0][1], xs0, wA.y, acc[0][1]);
        FMA_F32X2(acc[0][2], xs0, wB.x, acc[0][2]);
        FMA_F32X2(acc[0][3], xs0, wB.y, acc[0][3]);
        FMA_F32X2(acc[1][0], xs1, wA.x, acc[1][0]);
        FMA_F32X2(acc[1][1], xs1, wA.y, acc[1][1]);
        FMA_F32X2(acc[1][2], xs1, wB.x, acc[1][2]);
        FMA_F32X2(acc[1][3], xs1, wB.y, acc[1][3]);
        FMA_F32X2(acc[2][0], xs2, wA.x, acc[2][0]);
        FMA_F32X2(acc[2][1], xs2, wA.y, acc[2][1]);
        FMA_F32X2(acc[2][2], xs2, wB.x, acc[2][2]);
        FMA_F32X2(acc[2][3], xs2, wB.y, acc[2][3]);
        FMA_F32X2(acc[3][0], xs3, wA.x, acc[3][0]);
        FMA_F32X2(acc[3][1], xs3, wA.y, acc[3][1]);
        FMA_F32X2(acc[3][2], xs3, wB.x, acc[3][2]);
        FMA_F32X2(acc[3][3], xs3, wB.y, acc[3][3]);
    }

    // cross-group partial exchange through PB [pt][PBP]
    float* pb = sm + S_PB;
    if (group == 0) {
        #pragma unroll
        for (int p = 0; p < 4; p++) {
            ulonglong2 v; v.x = acc[p][2]; v.y = acc[p][3];
            *(ulonglong2*)(pb + (4 * ty + p) * PBP + 8 * tx + 4) = v;
        }
    } else {
        #pragma unroll
        for (int p = 0; p < 4; p++) {
            ulonglong2 v; v.x = acc[p][0]; v.y = acc[p][1];
            *(ulonglong2*)(pb + (4 * ty + p) * PBP + 8 * tx) = v;
        }
    }
    __syncthreads();

    const u64t* bp = (const u64t*)(sm + boff + 8 * tx);
    const int sel = group ? 2 : 0;                 // which acc pairs this group finalizes
    const int off = group ? 4 : 0;                 // PB read offset / neuron offset
    u64t bb0 = bp[sel], bb1 = bp[sel + 1];
    float vals[4][4];
    #pragma unroll
    for (int p = 0; p < 4; p++) {
        ulonglong2 o = *(const ulonglong2*)(pb + (4 * ty + p) * PBP + 8 * tx + off);
        u64t s0, s1;
        ADD_F32X2(s0, acc[p][sel], o.x);
        ADD_F32X2(s0, s0, bb0);
        ADD_F32X2(s1, acc[p][sel + 1], o.y);
        ADD_F32X2(s1, s1, bb1);
        unsigned int u0, u1, u2, u3;
        UNPACK_F32X2U(u0, u1, s0);
        UNPACK_F32X2U(u2, u3, s1);
        float v0 = __uint_as_float(u0), v1 = __uint_as_float(u1);
        float v2 = __uint_as_float(u2), v3 = __uint_as_float(u3);
        if (ACT) { v0 = sp_fast(v0); v1 = sp_fast(v1); v2 = sp_fast(v2); v3 = sp_fast(v3); }
        vals[p][0] = v0; vals[p][1] = v1; vals[p][2] = v2; vals[p][3] = v3;
    }
    float* yp = sm + yoff + 4 * ty;
    const int nbase = 8 * tx + off;
    #pragma unroll
    for (int j = 0; j < 4; j++) {
        *(float4*)(yp + (nbase + j) * PADP) =
            make_float4(vals[0][j], vals[1][j], vals[2][j], vals[3][j]);
    }
    __syncthreads();
}

__global__ __launch_bounds__(TPB, 1)
void nerf_mlp_ks_kernel(
    const float* __restrict__ embedded,
    const float* __restrict__ embedded_dir,
    const float* __restrict__ occ_W0, const float* __restrict__ occ_b0,
    const float* __restrict__ occ_W1, const float* __restrict__ occ_b1,
    const float* __restrict__ occ_W2, const float* __restrict__ occ_b2,
    const float* __restrict__ rgb_W0, const float* __restrict__ rgb_b0,
    const float* __restrict__ rgb_W1, const float* __restrict__ rgb_b1,
    const float* __restrict__ rgb_W2, const float* __restrict__ rgb_b2,
    const float* __restrict__ rgb_latent,
    const int*   __restrict__ latent_index,
    float* __restrict__ out)
{
    extern __shared__ float sm[];
    const int tid   = threadIdx.x;
    const int group = tid >> 8;
    const int tg    = tid & 255;

    // ---------- stage weights once ----------
    for (int t = tid; t < 32*64;  t += TPB) sm[S_OCCW0 + t] = occ_W0[t];
    for (int t = tid; t < 64*64;  t += TPB) sm[S_OCCW1 + t] = occ_W1[t];
    for (int t = tid; t < 64*16;  t += TPB) sm[S_OCCW2 + t] = occ_W2[t];
    for (int t = tid; t < 74*64;  t += TPB) sm[S_RGBW0 + t] = rgb_W0[t];
    for (int t = tid; t < 64*64;  t += TPB) sm[S_RGBW1 + t] = rgb_W1[t];
    for (int t = tid; t < 64*3;   t += TPB) sm[S_RGBW2 + t] = rgb_W2[t];
    if (tid < 64) {
        sm[S_OCCB0 + tid] = occ_b0[tid];
        sm[S_OCCB1 + tid] = occ_b1[tid];
        sm[S_RGBB1 + tid] = rgb_b1[tid];
    }
    if (tid >= 64 && tid < 80)  sm[S_OCCB2 + tid - 64] = occ_b2[tid - 64];
    if (tid >= 80 && tid < 83)  sm[S_RGBB2 + tid - 80] = rgb_b2[tid - 80];

    if (tid >= 448) {
        const int j = tid - 448;
        const int li = *latent_index;
        const float* lrow = rgb_latent + li * LAT;
        float acc = rgb_b0[j];
        #pragma unroll 8
        for (int l = 0; l < LAT; l++)
            acc = fmaf(lrow[l], rgb_W0[(RGBK + l) * 64 + j], acc);
        sm[S_LATB + j] = acc;
    }
    __syncthreads();

    float* pb = sm + S_PB;

    // ---------- persistent tile loop ----------
    for (int tile = blockIdx.x; tile < NTILES; tile += NCTA) {
        const int g0 = tile * TILE;

        // stage inputs (transposed)
        {
            const float* src = embedded + (size_t)g0 * EMB;
            for (int idx = tid; idx < TILE * EMB; idx += TPB) {
                int p = idx >> 5, k = idx & 31;
                sm[S_XB + k * PADP + p] = src[idx];
            }
            const float* sd = embedded_dir + (size_t)g0 * DIRD;
            for (int idx = tid; idx < TILE * DIRD; idx += TPB) {
                int p = idx / DIRD, k = idx - p * DIRD;
                sm[S_XB + (EMB + k) * PADP + p] = sd[idx];
            }
        }
        __syncthreads();

        // occ layer 0: 32 -> 64, softplus
        layer64_ks<EMB, true>(sm, S_XB, S_OCCW0, S_OCCB0, S_HB, tg, group);
        // occ layer 1: 64 -> 64, softplus
        layer64_ks<DH, true>(sm, S_HB, S_OCCW1, S_OCCB1, S_GB, tg, group);

        // occ layer 2: 64 -> 16 (linear), K-split, 1 thread/point (tg<128)
        {
            float acc[16];
            if (tg < TILE) {
                const int p  = tg;
                const int k0 = group ? 32 : 0;
                if (group == 0) {
                    #pragma unroll
                    for (int q = 0; q < 4; q++) {
                        float4 b = *(const float4*)(sm + S_OCCB2 + 4 * q);
                        acc[4*q+0] = b.x; acc[4*q+1] = b.y;
                        acc[4*q+2] = b.z; acc[4*q+3] = b.w;
                    }
                } else {
                    #pragma unroll
                    for (int q = 0; q < 16; q++) acc[q] = 0.0f;
                }
                const float* xp = sm + S_GB + p + k0 * PADP;
                const float* wp = sm + S_OCCW2 + k0 * 16;
                #pragma unroll 8
                for (int k = 0; k < 32; k++) {
                    float x = xp[k * PADP];
                    #pragma unroll
                    for (int q = 0; q < 4; q++) {
                        float4 w = *(const float4*)(wp + k * 16 + 4 * q);
                        acc[4*q+0] = fmaf(x, w.x, acc[4*q+0]);
                        acc[4*q+1] = fmaf(x, w.y, acc[4*q+1]);
                        acc[4*q+2] = fmaf(x, w.z, acc[4*q+2]);
                        acc[4*q+3] = fmaf(x, w.w, acc[4*q+3]);
                    }
                }
                if (group == 1) {
                    #pragma unroll
                    for (int q = 0; q < 4; q++)
                        *(float4*)(pb + p * PBP + 4 * q) =
                            make_float4(acc[4*q], acc[4*q+1], acc[4*q+2], acc[4*q+3]);
                }
            }
            __syncthreads();
            if (tg < TILE && group == 0) {
                const int p = tg;
                #pragma unroll
                for (int q = 0; q < 4; q++) {
                    float4 o = *(const float4*)(pb + p * PBP + 4 * q);
                    acc[4*q+0] += o.x; acc[4*q+1] += o.y;
                    acc[4*q+2] += o.z; acc[4*q+3] += o.w;
                }
                float oc = 1.0f - __expf(-sp_fast(acc[0]));
                sm[S_OCCV + p] = oc;
                out[(size_t)NPTS * 4 + g0 + p] = oc;
                #pragma unroll
                for (int n = 1; n < 16; n++)
                    sm[S_XB + (EMB + DIRD + n - 1) * PADP + p] = acc[n];
            }
            __syncthreads();
        }

        // rgb layer 0: 74 -> 64, softplus (latent-folded bias)
        layer64_ks<RGBK, true>(sm, S_XB, S_RGBW0, S_LATB, S_HB, tg, group);
        // rgb layer 1: 64 -> 64, softplus
        layer64_ks<DH, true>(sm, S_HB, S_RGBW1, S_RGBB1, S_GB, tg, group);

        // rgb layer 2: 64 -> 3 sigmoid, K-split, 1 thread/point
        {
            float a0 = 0.f, a1 = 0.f, a2 = 0.f;
            if (tg < TILE) {
                const int p  = tg;
                const int k0 = group ? 32 : 0;
                if (group == 0) {
                    a0 = sm[S_RGBB2 + 0]; a1 = sm[S_RGBB2 + 1]; a2 = sm[S_RGBB2 + 2];
                }
                const float* xp = sm + S_GB + p + k0 * PADP;
                const float* wp = sm + S_RGBW2 + k0 * 3;
                #pragma unroll 8
                for (int k = 0; k < 32; k++) {
                    float x = xp[k * PADP];
                    a0 = fmaf(x, wp[k * 3 + 0], a0);
                    a1 = fmaf(x, wp[k * 3 + 1], a1);
                    a2 = fmaf(x, wp[k * 3 + 2], a2);
                }
                if (group == 1)
                    *(float4*)(pb + p * PBP) = make_float4(a0, a1, a2, 0.0f);
            }
            __syncthreads();
            if (tg < TILE && group == 0) {
                const int p = tg;
                float4 o = *(const float4*)(pb + p * PBP);
                float4 raw = make_float4(sigmoid_fast(a0 + o.x),
                                         sigmoid_fast(a1 + o.y),
                                         sigmoid_fast(a2 + o.z),
                                         sm[S_OCCV + p]);
                reinterpret_cast<float4*>(out)[g0 + p] = raw;
            }
            __syncthreads();
        }
    }
}

extern "C" void kernel_launch(void* const* d_in, const int* in_sizes, int n_in,
                              void* d_out, int out_size) {
    const float* embedded     = (const float*)d_in[0];
    const float* embedded_dir = (const float*)d_in[1];
    const float* occ_W0 = (const float*)d_in[2];
    const float* occ_b0 = (const float*)d_in[3];
    const float* occ_W1 = (const float*)d_in[4];
    const float* occ_b1 = (const float*)d_in[5];
    const float* occ_W2 = (const float*)d_in[6];
    const float* occ_b2 = (const float*)d_in[7];
    const float* rgb_W0 = (const float*)d_in[8];
    const float* rgb_b0 = (const float*)d_in[9];
    const float* rgb_W1 = (const float*)d_in[10];
    const float* rgb_b1 = (const float*)d_in[11];
    const float* rgb_W2 = (const float*)d_in[12];
    const float* rgb_b2 = (const float*)d_in[13];
    const float* rgb_latent = (const float*)d_in[14];
    const int*   latent_index = (const int*)d_in[15];

    const size_t smem_bytes = (size_t)S_TOTAL * sizeof(float);
    cudaFuncSetAttribute(nerf_mlp_ks_kernel,
                         cudaFuncAttributeMaxDynamicSharedMemorySize,
                         (int)smem_bytes);

    nerf_mlp_ks_kernel<<<NCTA, TPB, smem_bytes>>>(
        embedded, embedded_dir,
        occ_W0, occ_b0, occ_W1, occ_b1, occ_W2, occ_b2,
        rgb_W0, rgb_b0, rgb_W1, rgb_b1, rgb_W2, rgb_b2,
        rgb_latent, latent_index,
        (float*)d_out);
}

// round 9
// speedup vs baseline: 1.2824x; 1.2824x over previous
#include <cuda_runtime.h>
#include <cstdint>

#define NPTS 524288
#define TPB  128
#define EMB  32
#define DIRD 27
#define FEAT 15
#define LAT  128
#define RGBK (EMB + DIRD + FEAT)   // 74

// ---- smem float offsets (weights + biases only; dynamic smem) ----
#define W0   0          // occ_W0 [32][64]
#define W1   2048       // occ_W1 [64][64]
#define W2   6144       // occ_W2 [64][16]
#define RW0  7168       // rgb_W0 rows 0..73 [74][64]
#define RW1  11904      // rgb_W1 [64][64]
#define RW2T 16000      // rgb_W2 transposed [3][64]
#define B0   16192
#define B1   16256
#define B2   16320      // 16
#define RB1  16336
#define RB2  16400      // 4 (3 used)
#define LATB 16404      // 64: rgb_b0 + latent @ rgb_W0[74:]
#define SMF  16468      // total floats = 65872 bytes

typedef unsigned long long u64t;

#define FMA_F32X2(d, a, b, c) \
    asm("fma.rn.f32x2 %0, %1, %2, %3;" : "=l"(d) : "l"(a), "l"(b), "l"(c))
#define PACK_SPLAT(out, x) \
    asm("mov.b64 %0, {%1, %1};" : "=l"(out) : "r"(__float_as_uint(x)))
#define UNPACK_F32X2U(lo, hi, in) \
    asm("mov.b64 {%0, %1}, %2;" : "=r"(lo), "=r"(hi) : "l"(in))

__device__ __forceinline__ float sp_fast(float x) {
    float e = __expf(x);
    float y = __logf(1.0f + e);
    return (x > 20.0f) ? x : y;
}
__device__ __forceinline__ float sigmoid_fast(float x) {
    return 1.0f / (1.0f + __expf(-x));
}

// y[64] = act(x[K] @ W[K][64] + b); x,y register arrays; W,b lane-uniform smem.
template<int K, bool ACT>
__device__ __forceinline__ void dense64(const float* x, const float* sw,
                                        const float* sb, float* y)
{
    u64t acc[32];
    const u64t* bp = (const u64t*)sb;
    #pragma unroll
    for (int q = 0; q < 32; q++) acc[q] = bp[q];

    #pragma unroll
    for (int k = 0; k < K; k++) {
        u64t xs;
        PACK_SPLAT(xs, x[k]);
        const ulonglong2* wr = (const ulonglong2*)(sw + k * 64);
        #pragma unroll
        for (int q = 0; q < 16; q++) {
            ulonglong2 w = wr[q];
            FMA_F32X2(acc[2*q],   xs, w.x, acc[2*q]);
            FMA_F32X2(acc[2*q+1], xs, w.y, acc[2*q+1]);
        }
    }

    #pragma unroll
    for (int q = 0; q < 32; q++) {
        unsigned lo, hi;
        UNPACK_F32X2U(lo, hi, acc[q]);
        float a = __uint_as_float(lo), b = __uint_as_float(hi);
        if (ACT) { a = sp_fast(a); b = sp_fast(b); }
        y[2*q]   = a;
        y[2*q+1] = b;
    }
}

__global__ __launch_bounds__(TPB, 2)
void nerf_tpp_kernel(
    const float* __restrict__ embedded,
    const float* __restrict__ embedded_dir,
    const float* __restrict__ occ_W0, const float* __restrict__ occ_b0,
    const float* __restrict__ occ_W1, const float* __restrict__ occ_b1,
    const float* __restrict__ occ_W2, const float* __restrict__ occ_b2,
    const float* __restrict__ rgb_W0, const float* __restrict__ rgb_b0,
    const float* __restrict__ rgb_W1, const float* __restrict__ rgb_b1,
    const float* __restrict__ rgb_W2, const float* __restrict__ rgb_b2,
    const float* __restrict__ rgb_latent,
    const int*   __restrict__ latent_index,
    float* __restrict__ out)
{
    extern __shared__ float sw[];
    const int tid = threadIdx.x;

    // ---- stage weights (broadcast-friendly layouts) ----
    for (int t = tid; t < 32*64; t += TPB) sw[W0  + t] = occ_W0[t];
    for (int t = tid; t < 64*64; t += TPB) sw[W1  + t] = occ_W1[t];
    for (int t = tid; t < 64*16; t += TPB) sw[W2  + t] = occ_W2[t];
    for (int t = tid; t < 74*64; t += TPB) sw[RW0 + t] = rgb_W0[t];
    for (int t = tid; t < 64*64; t += TPB) sw[RW1 + t] = rgb_W1[t];
    for (int t = tid; t < 64*3;  t += TPB) {
        int k = t / 3, j = t - 3 * k;
        sw[RW2T + j * 64 + k] = rgb_W2[t];     // transpose to [3][64]
    }
    if (tid < 64) {
        sw[B0  + tid] = occ_b0[tid];
        sw[B1  + tid] = occ_b1[tid];
        sw[RB1 + tid] = rgb_b1[tid];
    }
    if (tid >= 64 && tid < 80) sw[B2  + tid - 64] = occ_b2[tid - 64];
    if (tid >= 80 && tid < 83) sw[RB2 + tid - 80] = rgb_b2[tid - 80];
    if (tid >= 83 && tid < 84) sw[RB2 + 3] = 0.0f;

    // fold constant latent into rgb layer-0 bias
    if (tid >= 64) {
        const int j = tid - 64;
        const int li = *latent_index;
        const float* lrow = rgb_latent + li * LAT;
        float acc = rgb_b0[j];
        #pragma unroll 8
        for (int l = 0; l < LAT; l++)
            acc = fmaf(lrow[l], rgb_W0[(RGBK + l) * 64 + j], acc);
        sw[LATB + j] = acc;
    }
    __syncthreads();

    const int p = blockIdx.x * TPB + tid;

    // ---- per-point activations in registers ----
    float xr[RGBK];            // e | dir | feat (rgb layer-0 input)
    {
        const float4* e4 = reinterpret_cast<const float4*>(embedded + (size_t)p * EMB);
        #pragma unroll
        for (int q = 0; q < EMB/4; q++) {
            float4 v = e4[q];
            xr[4*q+0] = v.x; xr[4*q+1] = v.y; xr[4*q+2] = v.z; xr[4*q+3] = v.w;
        }
        const float* dp = embedded_dir + (size_t)p * DIRD;
        #pragma unroll
        for (int k = 0; k < DIRD; k++) xr[EMB + k] = dp[k];
    }

    float a1[64], a2[64];

    // occ layer 0: 32 -> 64 softplus
    dense64<EMB, true>(xr, sw + W0, sw + B0, a1);
    // occ layer 1: 64 -> 64 softplus
    dense64<64, true>(a1, sw + W1, sw + B1, a2);

    // occ layer 2: 64 -> 16 linear
    float occ;
    {
        u64t acc[8];
        const u64t* bp = (const u64t*)(sw + B2);
        #pragma unroll
        for (int q = 0; q < 8; q++) acc[q] = bp[q];
        #pragma unroll
        for (int k = 0; k < 64; k++) {
            u64t xs;
            PACK_SPLAT(xs, a2[k]);
            const ulonglong2* wr = (const ulonglong2*)(sw + W2 + k * 16);
            ulonglong2 w0 = wr[0], w1 = wr[1];
            FMA_F32X2(acc[0], xs, w0.x, acc[0]);
            FMA_F32X2(acc[1], xs, w0.y, acc[1]);
            FMA_F32X2(acc[2], xs, w1.x, acc[2]);
            FMA_F32X2(acc[3], xs, w1.y, acc[3]);
        }
        #pragma unroll
        for (int k = 0; k < 64; k++) {
            u64t xs;
            PACK_SPLAT(xs, a2[k]);
            const ulonglong2* wr = (const ulonglong2*)(sw + W2 + k * 16 + 8);
            ulonglong2 w0 = wr[0], w1 = wr[1];
            FMA_F32X2(acc[4], xs, w0.x, acc[4]);
            FMA_F32X2(acc[5], xs, w0.y, acc[5]);
            FMA_F32X2(acc[6], xs, w1.x, acc[6]);
            FMA_F32X2(acc[7], xs, w1.y, acc[7]);
        }
        float hid[16];
        #pragma unroll
        for (int q = 0; q < 8; q++) {
            unsigned lo, hi;
            UNPACK_F32X2U(lo, hi, acc[q]);
            hid[2*q]   = __uint_as_float(lo);
            hid[2*q+1] = __uint_as_float(hi);
        }
        occ = 1.0f - __expf(-sp_fast(hid[0]));
        #pragma unroll
        for (int n = 0; n < FEAT; n++) xr[EMB + DIRD + n] = hid[1 + n];
    }

    // rgb layer 0: 74 -> 64 softplus (latent-folded bias)
    dense64<RGBK, true>(xr, sw + RW0, sw + LATB, a1);
    // rgb layer 1: 64 -> 64 softplus
    dense64<64, true>(a1, sw + RW1, sw + RB1, a2);

    // rgb layer 2: 64 -> 3 sigmoid (RW2T rows contiguous over k)
    float rgbv[3];
    #pragma unroll
    for (int j = 0; j < 3; j++) {
        float acc = sw[RB2 + j];
        const float4* wr = (const float4*)(sw + RW2T + j * 64);
        #pragma unroll
        for (int q = 0; q < 16; q++) {
            float4 w = wr[q];
            acc = fmaf(a2[4*q+0], w.x, acc);
            acc = fmaf(a2[4*q+1], w.y, acc);
            acc = fmaf(a2[4*q+2], w.z, acc);
            acc = fmaf(a2[4*q+3], w.w, acc);
        }
        rgbv[j] = sigmoid_fast(acc);
    }

    // ---- outputs ----
    reinterpret_cast<float4*>(out)[p] = make_float4(rgbv[0], rgbv[1], rgbv[2], occ);
    out[(size_t)NPTS * 4 + p] = occ;
}

extern "C" void kernel_launch(void* const* d_in, const int* in_sizes, int n_in,
                              void* d_out, int out_size) {
    const float* embedded     = (const float*)d_in[0];
    const float* embedded_dir = (const float*)d_in[1];
    const float* occ_W0 = (const float*)d_in[2];
    const float* occ_b0 = (const float*)d_in[3];
    const float* occ_W1 = (const float*)d_in[4];
    const float* occ_b1 = (const float*)d_in[5];
    const float* occ_W2 = (const float*)d_in[6];
    const float* occ_b2 = (const float*)d_in[7];
    const float* rgb_W0 = (const float*)d_in[8];
    const float* rgb_b0 = (const float*)d_in[9];
    const float* rgb_W1 = (const float*)d_in[10];
    const float* rgb_b1 = (const float*)d_in[11];
    const float* rgb_W2 = (const float*)d_in[12];
    const float* rgb_b2 = (const float*)d_in[13];
    const float* rgb_latent = (const float*)d_in[14];
    const int*   latent_index = (const int*)d_in[15];

    const size_t smem_bytes = (size_t)SMF * sizeof(float);
    cudaFuncSetAttribute(nerf_tpp_kernel,
                         cudaFuncAttributeMaxDynamicSharedMemorySize,
                         (int)smem_bytes);

    nerf_tpp_kernel<<<NPTS / TPB, TPB, smem_bytes>>>(
        embedded, embedded_dir,
        occ_W0, occ_b0, occ_W1, occ_b1, occ_W2, occ_b2,
        rgb_W0, rgb_b0, rgb_W1, rgb_b1, rgb_W2, rgb_b2,
        rgb_latent, latent_index,
        (float*)d_out);
}

// round 10
// speedup vs baseline: 1.5127x; 1.1795x over previous
#include <cuda_runtime.h>
#include <cstdint>

#define NPTS 524288
#define TPB  128
#define EMB  32
#define DIRD 27
#define FEAT 15
#define LAT  128
#define RGBK (EMB + DIRD + FEAT)   // 74

// ---- smem float offsets (weights + biases only) ----
#define W0   0          // occ_W0 [32][64]
#define W1   2048       // occ_W1 [64][64]
#define W2   6144       // occ_W2 [64][16]
#define RW0  7168       // rgb_W0 rows 0..73 [74][64]
#define RW1  11904      // rgb_W1 [64][64]
#define RW2T 16000      // rgb_W2 transposed [3][64]
#define B0   16192
#define B1   16256
#define B2   16320      // 16
#define RB1  16336
#define RB2  16400      // 4 (3 used)
#define LATB 16404      // 64: rgb_b0 + latent @ rgb_W0[74:]
#define SMF  16468      // 65872 bytes

typedef unsigned long long u64t;

#define FMA_F32X2(d, a, b, c) \
    asm("fma.rn.f32x2 %0, %1, %2, %3;" : "=l"(d) : "l"(a), "l"(b), "l"(c))
#define PACK_SPLAT(out, x) \
    asm("mov.b64 %0, {%1, %1};" : "=l"(out) : "r"(__float_as_uint(x)))
#define UNPACK_F32X2U(lo, hi, in) \
    asm("mov.b64 {%0, %1}, %2;" : "=r"(lo), "=r"(hi) : "l"(in))

__device__ __forceinline__ float sp_fast(float x) {
    float e = __expf(x);
    float y = __logf(1.0f + e);
    return (x > 20.0f) ? x : y;
}
__device__ __forceinline__ float sigmoid_fast(float x) {
    return 1.0f / (1.0f + __expf(-x));
}

// y[32] = act(x[K] @ W[K][cols 32h..32h+31] + b_half)
// w = sw + Woff + 32*h (row stride 64); bias = (u64t*)(sw + Boff) + 16*h
template<int K, bool ACT>
__device__ __forceinline__ void dense32(const float* __restrict__ x,
                                        const float* __restrict__ w,
                                        const u64t* __restrict__ bias,
                                        float* __restrict__ y)
{
    u64t acc[16];
    #pragma unroll
    for (int q = 0; q < 16; q++) acc[q] = bias[q];

    #pragma unroll
    for (int k = 0; k < K; k++) {
        u64t xs;
        PACK_SPLAT(xs, x[k]);
        const ulonglong2* wr = (const ulonglong2*)(w + k * 64);
        #pragma unroll
        for (int q = 0; q < 8; q++) {
            ulonglong2 wv = wr[q];
            FMA_F32X2(acc[2*q],   xs, wv.x, acc[2*q]);
            FMA_F32X2(acc[2*q+1], xs, wv.y, acc[2*q+1]);
        }
    }

    #pragma unroll
    for (int q = 0; q < 16; q++) {
        unsigned lo, hi;
        UNPACK_F32X2U(lo, hi, acc[q]);
        float a = __uint_as_float(lo), b = __uint_as_float(hi);
        if (ACT) { a = sp_fast(a); b = sp_fast(b); }
        y[2*q]   = a;
        y[2*q+1] = b;
    }
}

// rgb layer-0 half: inputs e[32], d[27], f[15] against rows 0..73 of RW0
__device__ __forceinline__ void dense32_rgb(const float* __restrict__ e,
                                            const float* __restrict__ d,
                                            const float* __restrict__ f,
                                            const float* __restrict__ w,
                                            const u64t* __restrict__ bias,
                                            float* __restrict__ y)
{
    u64t acc[16];
    #pragma unroll
    for (int q = 0; q < 16; q++) acc[q] = bias[q];

    #pragma unroll
    for (int k = 0; k < EMB; k++) {
        u64t xs;
        PACK_SPLAT(xs, e[k]);
        const ulonglong2* wr = (const ulonglong2*)(w + k * 64);
        #pragma unroll
        for (int q = 0; q < 8; q++) {
            ulonglong2 wv = wr[q];
            FMA_F32X2(acc[2*q],   xs, wv.x, acc[2*q]);
            FMA_F32X2(acc[2*q+1], xs, wv.y, acc[2*q+1]);
        }
    }
    #pragma unroll
    for (int k = 0; k < DIRD; k++) {
        u64t xs;
        PACK_SPLAT(xs, d[k]);
        const ulonglong2* wr = (const ulonglong2*)(w + (EMB + k) * 64);
        #pragma unroll
        for (int q = 0; q < 8; q++) {
            ulonglong2 wv = wr[q];
            FMA_F32X2(acc[2*q],   xs, wv.x, acc[2*q]);
            FMA_F32X2(acc[2*q+1], xs, wv.y, acc[2*q+1]);
        }
    }
    #pragma unroll
    for (int k = 0; k < FEAT; k++) {
        u64t xs;
        PACK_SPLAT(xs, f[k]);
        const ulonglong2* wr = (const ulonglong2*)(w + (EMB + DIRD + k) * 64);
        #pragma unroll
        for (int q = 0; q < 8; q++) {
            ulonglong2 wv = wr[q];
            FMA_F32X2(acc[2*q],   xs, wv.x, acc[2*q]);
            FMA_F32X2(acc[2*q+1], xs, wv.y, acc[2*q+1]);
        }
    }

    #pragma unroll
    for (int q = 0; q < 16; q++) {
        unsigned lo, hi;
        UNPACK_F32X2U(lo, hi, acc[q]);
        y[2*q]   = sp_fast(__uint_as_float(lo));
        y[2*q+1] = sp_fast(__uint_as_float(hi));
    }
}

__global__ __launch_bounds__(TPB, 3)
void nerf_tpp3_kernel(
    const float* __restrict__ embedded,
    const float* __restrict__ embedded_dir,
    const float* __restrict__ occ_W0, const float* __restrict__ occ_b0,
    const float* __restrict__ occ_W1, const float* __restrict__ occ_b1,
    const float* __restrict__ occ_W2, const float* __restrict__ occ_b2,
    const float* __restrict__ rgb_W0, const float* __restrict__ rgb_b0,
    const float* __restrict__ rgb_W1, const float* __restrict__ rgb_b1,
    const float* __restrict__ rgb_W2, const float* __restrict__ rgb_b2,
    const float* __restrict__ rgb_latent,
    const int*   __restrict__ latent_index,
    float* __restrict__ out)
{
    extern __shared__ float sw[];
    const int tid = threadIdx.x;

    // ---- stage weights ----
    for (int t = tid; t < 32*64; t += TPB) sw[W0  + t] = occ_W0[t];
    for (int t = tid; t < 64*64; t += TPB) sw[W1  + t] = occ_W1[t];
    for (int t = tid; t < 64*16; t += TPB) sw[W2  + t] = occ_W2[t];
    for (int t = tid; t < 74*64; t += TPB) sw[RW0 + t] = rgb_W0[t];
    for (int t = tid; t < 64*64; t += TPB) sw[RW1 + t] = rgb_W1[t];
    for (int t = tid; t < 64*3;  t += TPB) {
        int k = t / 3, j = t - 3 * k;
        sw[RW2T + j * 64 + k] = rgb_W2[t];
    }
    if (tid < 64) {
        sw[B0  + tid] = occ_b0[tid];
        sw[B1  + tid] = occ_b1[tid];
        sw[RB1 + tid] = rgb_b1[tid];
    }
    if (tid >= 64 && tid < 80) sw[B2  + tid - 64] = occ_b2[tid - 64];
    if (tid >= 80 && tid < 83) sw[RB2 + tid - 80] = rgb_b2[tid - 80];
    if (tid == 83) sw[RB2 + 3] = 0.0f;

    // fold constant latent into rgb layer-0 bias
    if (tid >= 64) {
        const int j = tid - 64;
        const int li = *latent_index;
        const float* lrow = rgb_latent + li * LAT;
        float acc = rgb_b0[j];
        #pragma unroll 8
        for (int l = 0; l < LAT; l++)
            acc = fmaf(lrow[l], rgb_W0[(RGBK + l) * 64 + j], acc);
        sw[LATB + j] = acc;
    }
    __syncthreads();

    const int p = blockIdx.x * TPB + tid;

    float a[64], b[64];

    // ---- occ layer 0: 32 -> 64 softplus (e live only here) ----
    {
        float e[EMB];
        const float4* e4 = reinterpret_cast<const float4*>(embedded + (size_t)p * EMB);
        #pragma unroll
        for (int q = 0; q < EMB/4; q++) {
            float4 v = e4[q];
            e[4*q+0] = v.x; e[4*q+1] = v.y; e[4*q+2] = v.z; e[4*q+3] = v.w;
        }
        dense32<EMB, true>(e, sw + W0,      (const u64t*)(sw + B0),      a);
        dense32<EMB, true>(e, sw + W0 + 32, (const u64t*)(sw + B0) + 16, a + 32);
    }

    // ---- occ layer 1: 64 -> 64 softplus ----
    dense32<64, true>(a, sw + W1,      (const u64t*)(sw + B1),      b);
    dense32<64, true>(a, sw + W1 + 32, (const u64t*)(sw + B1) + 16, b + 32);

    // ---- occ layer 2: 64 -> 16 linear (single pass, acc 8 u64) ----
    float feat[FEAT];
    float occ;
    {
        u64t acc[8];
        const u64t* bp = (const u64t*)(sw + B2);
        #pragma unroll
        for (int q = 0; q < 8; q++) acc[q] = bp[q];
        #pragma unroll
        for (int k = 0; k < 64; k++) {
            u64t xs;
            PACK_SPLAT(xs, b[k]);
            const ulonglong2* wr = (const ulonglong2*)(sw + W2 + k * 16);
            ulonglong2 w0 = wr[0], w1 = wr[1];
            FMA_F32X2(acc[0], xs, w0.x, acc[0]);
            FMA_F32X2(acc[1], xs, w0.y, acc[1]);
            FMA_F32X2(acc[2], xs, w1.x, acc[2]);
            FMA_F32X2(acc[3], xs, w1.y, acc[3]);
        }
        #pragma unroll
        for (int k = 0; k < 64; k++) {
            u64t xs;
            PACK_SPLAT(xs, b[k]);
            const ulonglong2* wr = (const ulonglong2*)(sw + W2 + k * 16 + 8);
            ulonglong2 w0 = wr[0], w1 = wr[1];
            FMA_F32X2(acc[4], xs, w0.x, acc[4]);
            FMA_F32X2(acc[5], xs, w0.y, acc[5]);
            FMA_F32X2(acc[6], xs, w1.x, acc[6]);
            FMA_F32X2(acc[7], xs, w1.y, acc[7]);
        }
        float hid[16];
        #pragma unroll
        for (int q = 0; q < 8; q++) {
            unsigned lo, hi;
            UNPACK_F32X2U(lo, hi, acc[q]);
            hid[2*q]   = __uint_as_float(lo);
            hid[2*q+1] = __uint_as_float(hi);
        }
        occ = 1.0f - __expf(-sp_fast(hid[0]));
        #pragma unroll
        for (int n = 0; n < FEAT; n++) feat[n] = hid[1 + n];
    }

    // ---- rgb layer 0: 74 -> 64 softplus (reload e, load dir) ----
    {
        float e[EMB];
        const float4* e4 = reinterpret_cast<const float4*>(embedded + (size_t)p * EMB);
        #pragma unroll
        for (int q = 0; q < EMB/4; q++) {
            float4 v = __ldg(e4 + q);
            e[4*q+0] = v.x; e[4*q+1] = v.y; e[4*q+2] = v.z; e[4*q+3] = v.w;
        }
        float d[DIRD];
        const float* dp = embedded_dir + (size_t)p * DIRD;
        #pragma unroll
        for (int k = 0; k < DIRD; k++) d[k] = __ldg(dp + k);

        dense32_rgb(e, d, feat, sw + RW0,      (const u64t*)(sw + LATB),      a);
        dense32_rgb(e, d, feat, sw + RW0 + 32, (const u64t*)(sw + LATB) + 16, a + 32);
    }

    // ---- rgb layer 1: 64 -> 64 softplus ----
    dense32<64, true>(a, sw + RW1,      (const u64t*)(sw + RB1),      b);
    dense32<64, true>(a, sw + RW1 + 32, (const u64t*)(sw + RB1) + 16, b + 32);

    // ---- rgb layer 2: 64 -> 3 sigmoid ----
    float rgbv[3];
    #pragma unroll
    for (int j = 0; j < 3; j++) {
        float acc = sw[RB2 + j];
        const float4* wr = (const float4*)(sw + RW2T + j * 64);
        #pragma unroll
        for (int q = 0; q < 16; q++) {
            float4 w = wr[q];
            acc = fmaf(b[4*q+0], w.x, acc);
            acc = fmaf(b[4*q+1], w.y, acc);
            acc = fmaf(b[4*q+2], w.z, acc);
            acc = fmaf(b[4*q+3], w.w, acc);
        }
        rgbv[j] = sigmoid_fast(acc);
    }

    // ---- outputs ----
    reinterpret_cast<float4*>(out)[p] = make_float4(rgbv[0], rgbv[1], rgbv[2], occ);
    out[(size_t)NPTS * 4 + p] = occ;
}

extern "C" void kernel_launch(void* const* d_in, const int* in_sizes, int n_in,
                              void* d_out, int out_size) {
    const float* embedded     = (const float*)d_in[0];
    const float* embedded_dir = (const float*)d_in[1];
    const float* occ_W0 = (const float*)d_in[2];
    const float* occ_b0 = (const float*)d_in[3];
    const float* occ_W1 = (const float*)d_in[4];
    const float* occ_b1 = (const float*)d_in[5];
    const float* occ_W2 = (const float*)d_in[6];
    const float* occ_b2 = (const float*)d_in[7];
    const float* rgb_W0 = (const float*)d_in[8];
    const float* rgb_b0 = (const float*)d_in[9];
    const float* rgb_W1 = (const float*)d_in[10];
    const float* rgb_b1 = (const float*)d_in[11];
    const float* rgb_W2 = (const float*)d_in[12];
    const float* rgb_b2 = (const float*)d_in[13];
    const float* rgb_latent = (const float*)d_in[14];
    const int*   latent_index = (const int*)d_in[15];

    const size_t smem_bytes = (size_t)SMF * sizeof(float);
    cudaFuncSetAttribute(nerf_tpp3_kernel,
                         cudaFuncAttributeMaxDynamicSharedMemorySize,
                         (int)smem_bytes);

    nerf_tpp3_kernel<<<NPTS / TPB, TPB, smem_bytes>>>(
        embedded, embedded_dir,
        occ_W0, occ_b0, occ_W1, occ_b1, occ_W2, occ_b2,
        rgb_W0, rgb_b0, rgb_W1, rgb_b1, rgb_W2, rgb_b2,
        rgb_latent, latent_index,
        (float*)d_out);
}

// round 11
// speedup vs baseline: 1.5644x; 1.0342x over previous
#include <cuda_runtime.h>
#include <cstdint>

#define NPTS 524288
#define TPB  128
#define PBLK 256            // points per block (2 per thread)
#define EMB  32
#define DIRD 27
#define FEAT 15
#define LAT  128
#define RGBK (EMB + DIRD + FEAT)   // 74

// ---- smem float offsets ----
#define W0   0          // occ_W0 [32][64]
#define W1   2048       // occ_W1 [64][64]
#define W2   6144       // occ_W2 [64][16]
#define RW0  7168       // rgb_W0 rows 0..73 [74][64]
#define RW1  11904      // rgb_W1 [64][64]
#define RW2P 16000      // rgb_W2 padded [64][4]
#define B0   16256
#define B1   16320
#define B2   16384      // 16
#define RB1  16400
#define RB2  16464      // 4 (3 used)
#define LATB 16468      // 64
#define SMF  16532      // 66128 bytes

typedef unsigned long long u64t;

#define FMA_F32X2(d, a, b, c) \
    asm("fma.rn.f32x2 %0, %1, %2, %3;" : "=l"(d) : "l"(a), "l"(b), "l"(c))
#define PACK_SPLAT(out, x) \
    asm("mov.b64 %0, {%1, %1};" : "=l"(out) : "r"(__float_as_uint(x)))
#define UNPACK_F32X2U(lo, hi, in) \
    asm("mov.b64 {%0, %1}, %2;" : "=r"(lo), "=r"(hi) : "l"(in))

__device__ __forceinline__ float sp_fast(float x) {
    float e = __expf(x);
    float y = __logf(1.0f + e);
    return (x > 20.0f) ? x : y;
}
__device__ __forceinline__ float sigmoid_fast(float x) {
    return 1.0f / (1.0f + __expf(-x));
}

// Accumulate K input rows into full-width 64-neuron accs for TWO points.
// Weight row k at w + k*64; each 16B weight load feeds 4 FFMA2 (2 per point).
template<int K>
__device__ __forceinline__ void accum_full(const float* __restrict__ x0,
                                           const float* __restrict__ x1,
                                           const float* __restrict__ w,
                                           u64t* __restrict__ A0,
                                           u64t* __restrict__ A1)
{
    #pragma unroll
    for (int k = 0; k < K; k++) {
        u64t xs0, xs1;
        PACK_SPLAT(xs0, x0[k]);
        PACK_SPLAT(xs1, x1[k]);
        const ulonglong2* wr = (const ulonglong2*)(w + k * 64);
        #pragma unroll
        for (int t = 0; t < 16; t++) {
            ulonglong2 wv = wr[t];
            FMA_F32X2(A0[2*t],   xs0, wv.x, A0[2*t]);
            FMA_F32X2(A0[2*t+1], xs0, wv.y, A0[2*t+1]);
            FMA_F32X2(A1[2*t],   xs1, wv.x, A1[2*t]);
            FMA_F32X2(A1[2*t+1], xs1, wv.y, A1[2*t+1]);
        }
    }
}

__device__ __forceinline__ void unpack_sp32(const u64t* __restrict__ A,
                                            float* __restrict__ y)
{
    #pragma unroll
    for (int m = 0; m < 32; m++) {
        unsigned lo, hi;
        UNPACK_F32X2U(lo, hi, A[m]);
        y[2*m]   = sp_fast(__uint_as_float(lo));
        y[2*m+1] = sp_fast(__uint_as_float(hi));
    }
}
__device__ __forceinline__ void unpack_sp8(const u64t* __restrict__ A,
                                           float* __restrict__ y)
{
    #pragma unroll
    for (int m = 0; m < 8; m++) {
        unsigned lo, hi;
        UNPACK_F32X2U(lo, hi, A[m]);
        y[2*m]   = sp_fast(__uint_as_float(lo));
        y[2*m+1] = sp_fast(__uint_as_float(hi));
    }
}
__device__ __forceinline__ void unpack_lin8(const u64t* __restrict__ A,
                                            float* __restrict__ y)
{
    #pragma unroll
    for (int m = 0; m < 8; m++) {
        unsigned lo, hi;
        UNPACK_F32X2U(lo, hi, A[m]);
        y[2*m]   = __uint_as_float(lo);
        y[2*m+1] = __uint_as_float(hi);
    }
}

__global__ __launch_bounds__(TPB, 2)
void nerf_pp2_kernel(
    const float* __restrict__ embedded,
    const float* __restrict__ embedded_dir,
    const float* __restrict__ occ_W0, const float* __restrict__ occ_b0,
    const float* __restrict__ occ_W1, const float* __restrict__ occ_b1,
    const float* __restrict__ occ_W2, const float* __restrict__ occ_b2,
    const float* __restrict__ rgb_W0, const float* __restrict__ rgb_b0,
    const float* __restrict__ rgb_W1, const float* __restrict__ rgb_b1,
    const float* __restrict__ rgb_W2, const float* __restrict__ rgb_b2,
    const float* __restrict__ rgb_latent,
    const int*   __restrict__ latent_index,
    float* __restrict__ out)
{
    extern __shared__ float sw[];
    const int tid = threadIdx.x;

    // ---- stage weights ----
    for (int t = tid; t < 32*64; t += TPB) sw[W0  + t] = occ_W0[t];
    for (int t = tid; t < 64*64; t += TPB) sw[W1  + t] = occ_W1[t];
    for (int t = tid; t < 64*16; t += TPB) sw[W2  + t] = occ_W2[t];
    for (int t = tid; t < 74*64; t += TPB) sw[RW0 + t] = rgb_W0[t];
    for (int t = tid; t < 64*64; t += TPB) sw[RW1 + t] = rgb_W1[t];
    for (int t = tid; t < 64*3;  t += TPB) {
        int k = t / 3, j = t - 3 * k;
        sw[RW2P + k * 4 + j] = rgb_W2[t];
    }
    for (int t = tid; t < 64; t += TPB) sw[RW2P + t * 4 + 3] = 0.0f;
    if (tid < 64) {
        sw[B0  + tid] = occ_b0[tid];
        sw[B1  + tid] = occ_b1[tid];
        sw[RB1 + tid] = rgb_b1[tid];
    }
    if (tid >= 64 && tid < 80) sw[B2  + tid - 64] = occ_b2[tid - 64];
    if (tid >= 80 && tid < 83) sw[RB2 + tid - 80] = rgb_b2[tid - 80];
    if (tid == 83) sw[RB2 + 3] = 0.0f;

    // fold constant latent into rgb layer-0 bias
    if (tid >= 64) {
        const int j = tid - 64;
        const int li = *latent_index;
        const float* lrow = rgb_latent + li * LAT;
        float acc = rgb_b0[j];
        #pragma unroll 8
        for (int l = 0; l < LAT; l++)
            acc = fmaf(lrow[l], rgb_W0[(RGBK + l) * 64 + j], acc);
        sw[LATB + j] = acc;
    }
    __syncthreads();

    const int p0 = blockIdx.x * PBLK + tid;
    const int p1 = p0 + TPB;

    // ================= occ layer 0: 32 -> 64 softplus (full width) =========
    float a0[64], a1[64];
    {
        u64t A0[32], A1[32];
        const u64t* bp = (const u64t*)(sw + B0);
        #pragma unroll
        for (int m = 0; m < 32; m++) { A0[m] = bp[m]; A1[m] = bp[m]; }

        float e0[EMB], e1[EMB];
        {
            const float4* q0 = (const float4*)(embedded + (size_t)p0 * EMB);
            const float4* q1 = (const float4*)(embedded + (size_t)p1 * EMB);
            #pragma unroll
            for (int q = 0; q < EMB/4; q++) {
                float4 v0 = q0[q], v1 = q1[q];
                e0[4*q]=v0.x; e0[4*q+1]=v0.y; e0[4*q+2]=v0.z; e0[4*q+3]=v0.w;
                e1[4*q]=v1.x; e1[4*q+1]=v1.y; e1[4*q+2]=v1.z; e1[4*q+3]=v1.w;
            }
        }
        accum_full<EMB>(e0, e1, sw + W0, A0, A1);
        unpack_sp32(A0, a0);
        unpack_sp32(A1, a1);
    }

    // ===== occ layer 1 (64->64 sp) fused with occ layer 2 (64->16 lin) =====
    float hid0[16], hid1[16];
    {
        u64t C0[8], C1[8];
        const u64t* b2p = (const u64t*)(sw + B2);
        #pragma unroll
        for (int m = 0; m < 8; m++) { C0[m] = b2p[m]; C1[m] = b2p[m]; }

        #pragma unroll
        for (int q = 0; q < 4; q++) {
            u64t Q0[8], Q1[8];
            const u64t* b1p = (const u64t*)(sw + B1) + q * 8;
            #pragma unroll
            for (int m = 0; m < 8; m++) { Q0[m] = b1p[m]; Q1[m] = b1p[m]; }

            #pragma unroll
            for (int k = 0; k < 64; k++) {
                u64t xs0, xs1;
                PACK_SPLAT(xs0, a0[k]);
                PACK_SPLAT(xs1, a1[k]);
                const ulonglong2* wr = (const ulonglong2*)(sw + W1 + k*64 + q*16);
                ulonglong2 wA = wr[0], wB = wr[1];
                FMA_F32X2(Q0[0], xs0, wA.x, Q0[0]);
                FMA_F32X2(Q0[1], xs0, wA.y, Q0[1]);
                FMA_F32X2(Q0[2], xs0, wB.x, Q0[2]);
                FMA_F32X2(Q0[3], xs0, wB.y, Q0[3]);
                FMA_F32X2(Q1[0], xs1, wA.x, Q1[0]);
                FMA_F32X2(Q1[1], xs1, wA.y, Q1[1]);
                FMA_F32X2(Q1[2], xs1, wB.x, Q1[2]);
                FMA_F32X2(Q1[3], xs1, wB.y, Q1[3]);
                const ulonglong2* wr2 = (const ulonglong2*)(sw + W1 + k*64 + q*16 + 8);
                ulonglong2 wC = wr2[0], wD = wr2[1];
                FMA_F32X2(Q0[4], xs0, wC.x, Q0[4]);
                FMA_F32X2(Q0[5], xs0, wC.y, Q0[5]);
                FMA_F32X2(Q0[6], xs0, wD.x, Q0[6]);
                FMA_F32X2(Q0[7], xs0, wD.y, Q0[7]);
                FMA_F32X2(Q1[4], xs1, wC.x, Q1[4]);
                FMA_F32X2(Q1[5], xs1, wC.y, Q1[5]);
                FMA_F32X2(Q1[6], xs1, wD.x, Q1[6]);
                FMA_F32X2(Q1[7], xs1, wD.y, Q1[7]);
            }
            float h0[16], h1[16];
            unpack_sp8(Q0, h0);
            unpack_sp8(Q1, h1);

            // occL2 partial from this 16-neuron chunk
            #pragma unroll
            for (int kk = 0; kk < 16; kk++) {
                const int kq = q * 16 + kk;
                u64t xs0, xs1;
                PACK_SPLAT(xs0, h0[kk]);
                PACK_SPLAT(xs1, h1[kk]);
                const ulonglong2* wr = (const ulonglong2*)(sw + W2 + kq * 16);
                ulonglong2 wA = wr[0], wB = wr[1];
                FMA_F32X2(C0[0], xs0, wA.x, C0[0]);
                FMA_F32X2(C0[1], xs0, wA.y, C0[1]);
                FMA_F32X2(C0[2], xs0, wB.x, C0[2]);
                FMA_F32X2(C0[3], xs0, wB.y, C0[3]);
                FMA_F32X2(C1[0], xs1, wA.x, C1[0]);
                FMA_F32X2(C1[1], xs1, wA.y, C1[1]);
                FMA_F32X2(C1[2], xs1, wB.x, C1[2]);
                FMA_F32X2(C1[3], xs1, wB.y, C1[3]);
                const ulonglong2* wr2 = (const ulonglong2*)(sw + W2 + kq * 16 + 8);
                ulonglong2 wC = wr2[0], wD = wr2[1];
                FMA_F32X2(C0[4], xs0, wC.x, C0[4]);
                FMA_F32X2(C0[5], xs0, wC.y, C0[5]);
                FMA_F32X2(C0[6], xs0, wD.x, C0[6]);
                FMA_F32X2(C0[7], xs0, wD.y, C0[7]);
                FMA_F32X2(C1[4], xs1, wC.x, C1[4]);
                FMA_F32X2(C1[5], xs1, wC.y, C1[5]);
                FMA_F32X2(C1[6], xs1, wD.x, C1[6]);
                FMA_F32X2(C1[7], xs1, wD.y, C1[7]);
            }
        }
        unpack_lin8(C0, hid0);
        unpack_lin8(C1, hid1);
    }
    const float occ0 = 1.0f - __expf(-sp_fast(hid0[0]));
    const float occ1 = 1.0f - __expf(-sp_fast(hid1[0]));

    // ====== rgb layer 0: 74 -> 64 softplus, full width, sections f|e|d =====
    float r0[64], r1[64];
    {
        u64t A0[32], A1[32];
        const u64t* bp = (const u64t*)(sw + LATB);
        #pragma unroll
        for (int m = 0; m < 32; m++) { A0[m] = bp[m]; A1[m] = bp[m]; }

        // feat section (rows 59..73); hid[1..15]
        accum_full<FEAT>(hid0 + 1, hid1 + 1, sw + RW0 + (EMB + DIRD) * 64, A0, A1);

        // e section (rows 0..31), reloaded from gmem
        {
            float e0[EMB], e1[EMB];
            const float4* q0 = (const float4*)(embedded + (size_t)p0 * EMB);
            const float4* q1 = (const float4*)(embedded + (size_t)p1 * EMB);
            #pragma unroll
            for (int q = 0; q < EMB/4; q++) {
                float4 v0 = __ldg(q0 + q), v1 = __ldg(q1 + q);
                e0[4*q]=v0.x; e0[4*q+1]=v0.y; e0[4*q+2]=v0.z; e0[4*q+3]=v0.w;
                e1[4*q]=v1.x; e1[4*q+1]=v1.y; e1[4*q+2]=v1.z; e1[4*q+3]=v1.w;
            }
            accum_full<EMB>(e0, e1, sw + RW0, A0, A1);
        }

        // dir section (rows 32..58)
        {
            float d0[DIRD], d1[DIRD];
            const float* q0 = embedded_dir + (size_t)p0 * DIRD;
            const float* q1 = embedded_dir + (size_t)p1 * DIRD;
            #pragma unroll
            for (int k = 0; k < DIRD; k++) { d0[k] = __ldg(q0 + k); d1[k] = __ldg(q1 + k); }
            accum_full<DIRD>(d0, d1, sw + RW0 + EMB * 64, A0, A1);
        }

        unpack_sp32(A0, r0);
        unpack_sp32(A1, r1);
    }

    // ====== rgb layer 1 (64->64 sp) fused with rgb layer 2 (64->3 sig) ====
    float c00 = sw[RB2 + 0], c01 = sw[RB2 + 1], c02 = sw[RB2 + 2];
    float c10 = c00, c11 = c01, c12 = c02;
    {
        #pragma unroll
        for (int q = 0; q < 4; q++) {
            u64t Q0[8], Q1[8];
            const u64t* b1p = (const u64t*)(sw + RB1) + q * 8;
            #pragma unroll
            for (int m = 0; m < 8; m++) { Q0[m] = b1p[m]; Q1[m] = b1p[m]; }

            #pragma unroll
            for (int k = 0; k < 64; k++) {
                u64t xs0, xs1;
                PACK_SPLAT(xs0, r0[k]);
                PACK_SPLAT(xs1, r1[k]);
                const ulonglong2* wr = (const ulonglong2*)(sw + RW1 + k*64 + q*16);
                ulonglong2 wA = wr[0], wB = wr[1];
                FMA_F32X2(Q0[0], xs0, wA.x, Q0[0]);
                FMA_F32X2(Q0[1], xs0, wA.y, Q0[1]);
                FMA_F32X2(Q0[2], xs0, wB.x, Q0[2]);
                FMA_F32X2(Q0[3], xs0, wB.y, Q0[3]);
                FMA_F32X2(Q1[0], xs1, wA.x, Q1[0]);
                FMA_F32X2(Q1[1], xs1, wA.y, Q1[1]);
                FMA_F32X2(Q1[2], xs1, wB.x, Q1[2]);
                FMA_F32X2(Q1[3], xs1, wB.y, Q1[3]);
                const ulonglong2* wr2 = (const ulonglong2*)(sw + RW1 + k*64 + q*16 + 8);
                ulonglong2 wC = wr2[0], wD = wr2[1];
                FMA_F32X2(Q0[4], xs0, wC.x, Q0[4]);
                FMA_F32X2(Q0[5], xs0, wC.y, Q0[5]);
                FMA_F32X2(Q0[6], xs0, wD.x, Q0[6]);
                FMA_F32X2(Q0[7], xs0, wD.y, Q0[7]);
                FMA_F32X2(Q1[4], xs1, wC.x, Q1[4]);
                FMA_F32X2(Q1[5], xs1, wC.y, Q1[5]);
                FMA_F32X2(Q1[6], xs1, wD.x, Q1[6]);
                FMA_F32X2(Q1[7], xs1, wD.y, Q1[7]);
            }
            float h0[16], h1[16];
            unpack_sp8(Q0, h0);
            unpack_sp8(Q1, h1);

            // rgb2 partial from this 16-neuron chunk (RW2P padded rows)
            #pragma unroll
            for (int kk = 0; kk < 16; kk++) {
                const int kq = q * 16 + kk;
                float4 w = *(const float4*)(sw + RW2P + kq * 4);
                c00 = fmaf(h0[kk], w.x, c00);
                c01 = fmaf(h0[kk], w.y, c01);
                c02 = fmaf(h0[kk], w.z, c02);
                c10 = fmaf(h1[kk], w.x, c10);
                c11 = fmaf(h1[kk], w.y, c11);
                c12 = fmaf(h1[kk], w.z, c12);
            }
        }
    }

    // ---- outputs ----
    reinterpret_cast<float4*>(out)[p0] =
        make_float4(sigmoid_fast(c00), sigmoid_fast(c01), sigmoid_fast(c02), occ0);
    reinterpret_cast<float4*>(out)[p1] =
        make_float4(sigmoid_fast(c10), sigmoid_fast(c11), sigmoid_fast(c12), occ1);
    out[(size_t)NPTS * 4 + p0] = occ0;
    out[(size_t)NPTS * 4 + p1] = occ1;
}

extern "C" void kernel_launch(void* const* d_in, const int* in_sizes, int n_in,
                              void* d_out, int out_size) {
    const float* embedded     = (const float*)d_in[0];
    const float* embedded_dir = (const float*)d_in[1];
    const float* occ_W0 = (const float*)d_in[2];
    const float* occ_b0 = (const float*)d_in[3];
    const float* occ_W1 = (const float*)d_in[4];
    const float* occ_b1 = (const float*)d_in[5];
    const float* occ_W2 = (const float*)d_in[6];
    const float* occ_b2 = (const float*)d_in[7];
    const float* rgb_W0 = (const float*)d_in[8];
    const float* rgb_b0 = (const float*)d_in[9];
    const float* rgb_W1 = (const float*)d_in[10];
    const float* rgb_b1 = (const float*)d_in[11];
    const float* rgb_W2 = (const float*)d_in[12];
    const float* rgb_b2 = (const float*)d_in[13];
    const float* rgb_latent = (const float*)d_in[14];
    const int*   latent_index = (const int*)d_in[15];

    const size_t smem_bytes = (size_t)SMF * sizeof(float);
    cudaFuncSetAttribute(nerf_pp2_kernel,
                         cudaFuncAttributeMaxDynamicSharedMemorySize,
                         (int)smem_bytes);

    nerf_pp2_kernel<<<NPTS / PBLK, TPB, smem_bytes>>>(
        embedded, embedded_dir,
        occ_W0, occ_b0, occ_W1, occ_b1, occ_W2, occ_b2,
        rgb_W0, rgb_b0, rgb_W1, rgb_b1, rgb_W2, rgb_b2,
        rgb_latent, latent_index,
        (float*)d_out);
}

// round 12
// speedup vs baseline: 1.6258x; 1.0393x over previous
#include <cuda_runtime.h>
#include <cstdint>

#define NPTS 524288
#define TPB  128
#define EMB  32
#define DIRD 27
#define FEAT 15
#define LAT  128
#define RGBK (EMB + DIRD + FEAT)   // 74

// ---- phase 1 smem float offsets (occ net) ----
#define P1_W0 0          // occ_W0 [32][64]
#define P1_W1 2048       // occ_W1 [64][64]
#define P1_W2 6144       // occ_W2 [64][16]
#define P1_B0 7168
#define P1_B1 7232
#define P1_B2 7296       // 16
// ---- phase 2 smem float offsets (rgb net) ----
#define P2_RW0  0        // rgb_W0 rows 0..73 [74][64]
#define P2_RW1  4736     // rgb_W1 [64][64]
#define P2_RW2P 8832     // rgb_W2 padded [64][4]
#define P2_LATB 9088     // 64
#define P2_RB1  9152     // 64
#define P2_RB2  9216     // 4
#define SMF     9220     // 36880 bytes

// scratch: [occ | feat*15] per point
__device__ float g_feat[(size_t)NPTS * 16];

typedef unsigned long long u64t;

#define FMA_F32X2(d, a, b, c) \
    asm("fma.rn.f32x2 %0, %1, %2, %3;" : "=l"(d) : "l"(a), "l"(b), "l"(c))
#define PACK_SPLAT(out, x) \
    asm("mov.b64 %0, {%1, %1};" : "=l"(out) : "r"(__float_as_uint(x)))
#define UNPACK_F32X2U(lo, hi, in) \
    asm("mov.b64 {%0, %1}, %2;" : "=r"(lo), "=r"(hi) : "l"(in))

__device__ __forceinline__ float sp_fast(float x) {
    float e = __expf(x);
    float y = __logf(1.0f + e);
    return (x > 20.0f) ? x : y;
}
__device__ __forceinline__ float sigmoid_fast(float x) {
    return 1.0f / (1.0f + __expf(-x));
}

// A[32 u64] += sum_k x[k] * Wrow(k)  (full 64-neuron width, one point)
template<int K>
__device__ __forceinline__ void accum64(const float* __restrict__ x,
                                        const float* __restrict__ w,
                                        u64t* __restrict__ A)
{
    #pragma unroll
    for (int k = 0; k < K; k++) {
        u64t xs;
        PACK_SPLAT(xs, x[k]);
        const ulonglong2* wr = (const ulonglong2*)(w + k * 64);
        #pragma unroll
        for (int t = 0; t < 16; t++) {
            ulonglong2 wv = wr[t];
            FMA_F32X2(A[2*t],   xs, wv.x, A[2*t]);
            FMA_F32X2(A[2*t+1], xs, wv.y, A[2*t+1]);
        }
    }
}

__device__ __forceinline__ void unpack_sp64(const u64t* __restrict__ A,
                                            float* __restrict__ y)
{
    #pragma unroll
    for (int m = 0; m < 32; m++) {
        unsigned lo, hi;
        UNPACK_F32X2U(lo, hi, A[m]);
        y[2*m]   = sp_fast(__uint_as_float(lo));
        y[2*m+1] = sp_fast(__uint_as_float(hi));
    }
}

__global__ __launch_bounds__(TPB, 4)
void nerf_ps_kernel(
    const float* __restrict__ embedded,
    const float* __restrict__ embedded_dir,
    const float* __restrict__ occ_W0, const float* __restrict__ occ_b0,
    const float* __restrict__ occ_W1, const float* __restrict__ occ_b1,
    const float* __restrict__ occ_W2, const float* __restrict__ occ_b2,
    const float* __restrict__ rgb_W0, const float* __restrict__ rgb_b0,
    const float* __restrict__ rgb_W1, const float* __restrict__ rgb_b1,
    const float* __restrict__ rgb_W2, const float* __restrict__ rgb_b2,
    const float* __restrict__ rgb_latent,
    const int*   __restrict__ latent_index,
    float* __restrict__ out)
{
    extern __shared__ float sw[];
    const int tid = threadIdx.x;
    const int p   = blockIdx.x * TPB + tid;

    // ================= PHASE 1: occ net =================
    for (int t = tid; t < 32*64; t += TPB) sw[P1_W0 + t] = occ_W0[t];
    for (int t = tid; t < 64*64; t += TPB) sw[P1_W1 + t] = occ_W1[t];
    for (int t = tid; t < 64*16; t += TPB) sw[P1_W2 + t] = occ_W2[t];
    if (tid < 64) {
        sw[P1_B0 + tid] = occ_b0[tid];
        sw[P1_B1 + tid] = occ_b1[tid];
    }
    if (tid >= 64 && tid < 80) sw[P1_B2 + tid - 64] = occ_b2[tid - 64];
    __syncthreads();

    float hid[16];
    {
        // occ layer 0: 32 -> 64 softplus
        float a[64];
        {
            u64t A[32];
            const u64t* bp = (const u64t*)(sw + P1_B0);
            #pragma unroll
            for (int m = 0; m < 32; m++) A[m] = bp[m];

            float e[EMB];
            const float4* e4 = (const float4*)(embedded + (size_t)p * EMB);
            #pragma unroll
            for (int q = 0; q < EMB/4; q++) {
                float4 v = e4[q];
                e[4*q]=v.x; e[4*q+1]=v.y; e[4*q+2]=v.z; e[4*q+3]=v.w;
            }
            accum64<EMB>(e, sw + P1_W0, A);
            unpack_sp64(A, a);
        }

        // fused occ layer 1 (64->64 sp) + occ layer 2 (64->16 lin)
        u64t C[8];
        const u64t* b2p = (const u64t*)(sw + P1_B2);
        #pragma unroll
        for (int m = 0; m < 8; m++) C[m] = b2p[m];

        #pragma unroll
        for (int q = 0; q < 4; q++) {
            u64t Q[8];
            const u64t* b1p = (const u64t*)(sw + P1_B1) + q * 8;
            #pragma unroll
            for (int m = 0; m < 8; m++) Q[m] = b1p[m];

            #pragma unroll
            for (int k = 0; k < 64; k++) {
                u64t xs;
                PACK_SPLAT(xs, a[k]);
                const ulonglong2* wr = (const ulonglong2*)(sw + P1_W1 + k*64 + q*16);
                ulonglong2 wA = wr[0], wB = wr[1];
                FMA_F32X2(Q[0], xs, wA.x, Q[0]);
                FMA_F32X2(Q[1], xs, wA.y, Q[1]);
                FMA_F32X2(Q[2], xs, wB.x, Q[2]);
                FMA_F32X2(Q[3], xs, wB.y, Q[3]);
                const ulonglong2* wr2 = (const ulonglong2*)(sw + P1_W1 + k*64 + q*16 + 8);
                ulonglong2 wC = wr2[0], wD = wr2[1];
                FMA_F32X2(Q[4], xs, wC.x, Q[4]);
                FMA_F32X2(Q[5], xs, wC.y, Q[5]);
                FMA_F32X2(Q[6], xs, wD.x, Q[6]);
                FMA_F32X2(Q[7], xs, wD.y, Q[7]);
            }
            float h[16];
            #pragma unroll
            for (int m = 0; m < 8; m++) {
                unsigned lo, hi;
                UNPACK_F32X2U(lo, hi, Q[m]);
                h[2*m]   = sp_fast(__uint_as_float(lo));
                h[2*m+1] = sp_fast(__uint_as_float(hi));
            }
            #pragma unroll
            for (int kk = 0; kk < 16; kk++) {
                const int kq = q * 16 + kk;
                u64t xs;
                PACK_SPLAT(xs, h[kk]);
                const ulonglong2* wr = (const ulonglong2*)(sw + P1_W2 + kq * 16);
                ulonglong2 wA = wr[0], wB = wr[1];
                FMA_F32X2(C[0], xs, wA.x, C[0]);
                FMA_F32X2(C[1], xs, wA.y, C[1]);
                FMA_F32X2(C[2], xs, wB.x, C[2]);
                FMA_F32X2(C[3], xs, wB.y, C[3]);
                const ulonglong2* wr2 = (const ulonglong2*)(sw + P1_W2 + kq * 16 + 8);
                ulonglong2 wC = wr2[0], wD = wr2[1];
                FMA_F32X2(C[4], xs, wC.x, C[4]);
                FMA_F32X2(C[5], xs, wC.y, C[5]);
                FMA_F32X2(C[6], xs, wD.x, C[6]);
                FMA_F32X2(C[7], xs, wD.y, C[7]);
            }
        }
        #pragma unroll
        for (int m = 0; m < 8; m++) {
            unsigned lo, hi;
            UNPACK_F32X2U(lo, hi, C[m]);
            hid[2*m]   = __uint_as_float(lo);
            hid[2*m+1] = __uint_as_float(hi);
        }
    }
    const float occv = 1.0f - __expf(-sp_fast(hid[0]));

    // write scratch [occ | feat15]
    {
        float4* g4 = (float4*)(g_feat + (size_t)p * 16);
        g4[0] = make_float4(occv, hid[1], hid[2], hid[3]);
        g4[1] = make_float4(hid[4], hid[5], hid[6], hid[7]);
        g4[2] = make_float4(hid[8], hid[9], hid[10], hid[11]);
        g4[3] = make_float4(hid[12], hid[13], hid[14], hid[15]);
    }

    // ================= PHASE 2: rgb net =================
    __syncthreads();   // all phase-1 smem reads done before restage
    for (int t = tid; t < 74*64; t += TPB) sw[P2_RW0 + t] = rgb_W0[t];
    for (int t = tid; t < 64*64; t += TPB) sw[P2_RW1 + t] = rgb_W1[t];
    for (int t = tid; t < 64*3;  t += TPB) {
        int k = t / 3, j = t - 3 * k;
        sw[P2_RW2P + k * 4 + j] = rgb_W2[t];
    }
    for (int t = tid; t < 64; t += TPB) sw[P2_RW2P + t * 4 + 3] = 0.0f;
    if (tid < 64) sw[P2_RB1 + tid] = rgb_b1[tid];
    if (tid >= 64 && tid < 67) sw[P2_RB2 + tid - 64] = rgb_b2[tid - 64];
    if (tid == 67) sw[P2_RB2 + 3] = 0.0f;
    // latent fold into rgb0 bias
    if (tid >= 64) {
        const int j = tid - 64;
        const int li = *latent_index;
        const float* lrow = rgb_latent + li * LAT;
        float acc = rgb_b0[j];
        #pragma unroll 8
        for (int l = 0; l < LAT; l++)
            acc = fmaf(lrow[l], rgb_W0[(RGBK + l) * 64 + j], acc);
        sw[P2_LATB + j] = acc;
    }
    __syncthreads();

    // reload scratch (f[0]=occ, f[1..15]=feat)
    float f[16];
    {
        const float4* g4 = (const float4*)(g_feat + (size_t)p * 16);
        #pragma unroll
        for (int q = 0; q < 4; q++) {
            float4 v = g4[q];
            f[4*q]=v.x; f[4*q+1]=v.y; f[4*q+2]=v.z; f[4*q+3]=v.w;
        }
    }

    // rgb layer 0: 74 -> 64 softplus (latent-folded bias), sectioned inputs
    float r[64];
    {
        u64t A[32];
        const u64t* bp = (const u64t*)(sw + P2_LATB);
        #pragma unroll
        for (int m = 0; m < 32; m++) A[m] = bp[m];

        // feat section rows 59..73
        accum64<FEAT>(f + 1, sw + P2_RW0 + (EMB + DIRD) * 64, A);

        // e section rows 0..31
        {
            float e[EMB];
            const float4* e4 = (const float4*)(embedded + (size_t)p * EMB);
            #pragma unroll
            for (int q = 0; q < EMB/4; q++) {
                float4 v = __ldg(e4 + q);
                e[4*q]=v.x; e[4*q+1]=v.y; e[4*q+2]=v.z; e[4*q+3]=v.w;
            }
            accum64<EMB>(e, sw + P2_RW0, A);
        }
        // dir section rows 32..58
        {
            float d[DIRD];
            const float* dp = embedded_dir + (size_t)p * DIRD;
            #pragma unroll
            for (int k = 0; k < DIRD; k++) d[k] = __ldg(dp + k);
            accum64<DIRD>(d, sw + P2_RW0 + EMB * 64, A);
        }
        unpack_sp64(A, r);
    }

    // fused rgb layer 1 (64->64 sp) + rgb layer 2 (64->3 sigmoid)
    float c0 = sw[P2_RB2 + 0], c1 = sw[P2_RB2 + 1], c2 = sw[P2_RB2 + 2];
    #pragma unroll
    for (int q = 0; q < 4; q++) {
        u64t Q[8];
        const u64t* b1p = (const u64t*)(sw + P2_RB1) + q * 8;
        #pragma unroll
        for (int m = 0; m < 8; m++) Q[m] = b1p[m];

        #pragma unroll
        for (int k = 0; k < 64; k++) {
            u64t xs;
            PACK_SPLAT(xs, r[k]);
            const ulonglong2* wr = (const ulonglong2*)(sw + P2_RW1 + k*64 + q*16);
            ulonglong2 wA = wr[0], wB = wr[1];
            FMA_F32X2(Q[0], xs, wA.x, Q[0]);
            FMA_F32X2(Q[1], xs, wA.y, Q[1]);
            FMA_F32X2(Q[2], xs, wB.x, Q[2]);
            FMA_F32X2(Q[3], xs, wB.y, Q[3]);
            const ulonglong2* wr2 = (const ulonglong2*)(sw + P2_RW1 + k*64 + q*16 + 8);
            ulonglong2 wC = wr2[0], wD = wr2[1];
            FMA_F32X2(Q[4], xs, wC.x, Q[4]);
            FMA_F32X2(Q[5], xs, wC.y, Q[5]);
            FMA_F32X2(Q[6], xs, wD.x, Q[6]);
            FMA_F32X2(Q[7], xs, wD.y, Q[7]);
        }
        float h[16];
        #pragma unroll
        for (int m = 0; m < 8; m++) {
            unsigned lo, hi;
            UNPACK_F32X2U(lo, hi, Q[m]);
            h[2*m]   = sp_fast(__uint_as_float(lo));
            h[2*m+1] = sp_fast(__uint_as_float(hi));
        }
        #pragma unroll
        for (int kk = 0; kk < 16; kk++) {
            const int kq = q * 16 + kk;
            float4 w = *(const float4*)(sw + P2_RW2P + kq * 4);
            c0 = fmaf(h[kk], w.x, c0);
            c1 = fmaf(h[kk], w.y, c1);
            c2 = fmaf(h[kk], w.z, c2);
        }
    }

    // ---- outputs ----
    reinterpret_cast<float4*>(out)[p] =
        make_float4(sigmoid_fast(c0), sigmoid_fast(c1), sigmoid_fast(c2), f[0]);
    out[(size_t)NPTS * 4 + p] = f[0];
}

extern "C" void kernel_launch(void* const* d_in, const int* in_sizes, int n_in,
                              void* d_out, int out_size) {
    const float* embedded     = (const float*)d_in[0];
    const float* embedded_dir = (const float*)d_in[1];
    const float* occ_W0 = (const float*)d_in[2];
    const float* occ_b0 = (const float*)d_in[3];
    const float* occ_W1 = (const float*)d_in[4];
    const float* occ_b1 = (const float*)d_in[5];
    const float* occ_W2 = (const float*)d_in[6];
    const float* occ_b2 = (const float*)d_in[7];
    const float* rgb_W0 = (const float*)d_in[8];
    const float* rgb_b0 = (const float*)d_in[9];
    const float* rgb_W1 = (const float*)d_in[10];
    const float* rgb_b1 = (const float*)d_in[11];
    const float* rgb_W2 = (const float*)d_in[12];
    const float* rgb_b2 = (const float*)d_in[13];
    const float* rgb_latent = (const float*)d_in[14];
    const int*   latent_index = (const int*)d_in[15];

    const size_t smem_bytes = (size_t)SMF * sizeof(float);
    cudaFuncSetAttribute(nerf_ps_kernel,
                         cudaFuncAttributeMaxDynamicSharedMemorySize,
                         (int)smem_bytes);

    nerf_ps_kernel<<<NPTS / TPB, TPB, smem_bytes>>>(
        embedded, embedded_dir,
        occ_W0, occ_b0, occ_W1, occ_b1, occ_W2, occ_b2,
        rgb_W0, rgb_b0, rgb_W1, rgb_b1, rgb_W2, rgb_b2,
        rgb_latent, latent_index,
        (float*)d_out);
}

// round 13
// speedup vs baseline: 1.9842x; 1.2205x over previous
#include <cuda_runtime.h>
#include <cstdint>

#define NPTS 524288
#define TPB  128
#define EMB  32
#define DIRD 27
#define FEAT 15
#define LAT  128
#define RGBK (EMB + DIRD + FEAT)   // 74
#define X2K  (DIRD + FEAT)         // 42 streamed rows for rgb0

// transposed inter-layer scratch [k][pt]
__device__ float g_a[64ULL * NPTS];    // occ L0 outputs
__device__ float g_x2[42ULL * NPTS];   // dir rows 0..26 | feat rows 27..41
__device__ float g_r[64ULL * NPTS];    // rgb L1 inputs' outputs (rgb0 out)

typedef unsigned long long u64t;

#define FMA_F32X2(d, a, b, c) \
    asm("fma.rn.f32x2 %0, %1, %2, %3;" : "=l"(d) : "l"(a), "l"(b), "l"(c))
#define PACK_SPLAT(out, x) \
    asm("mov.b64 %0, {%1, %1};" : "=l"(out) : "r"(__float_as_uint(x)))
#define UNPACK_F32X2U(lo, hi, in) \
    asm("mov.b64 {%0, %1}, %2;" : "=r"(lo), "=r"(hi) : "l"(in))

__device__ __forceinline__ float sp_fast(float x) {
    float e = __expf(x);
    float y = __logf(1.0f + e);
    return (x > 20.0f) ? x : y;
}
__device__ __forceinline__ float sigmoid_fast(float x) {
    return 1.0f / (1.0f + __expf(-x));
}

// 16-neuron quarter FMA step for 2 points: 4 LDS.128 : 16 FFMA2
#define QSTEP(Q0, Q1, xs0, xs1, wptr) do { \
    const ulonglong2* _wr = (const ulonglong2*)(wptr); \
    ulonglong2 _wa = _wr[0], _wb = _wr[1], _wc = _wr[2], _wd = _wr[3]; \
    FMA_F32X2(Q0[0], xs0, _wa.x, Q0[0]); \
    FMA_F32X2(Q0[1], xs0, _wa.y, Q0[1]); \
    FMA_F32X2(Q0[2], xs0, _wb.x, Q0[2]); \
    FMA_F32X2(Q0[3], xs0, _wb.y, Q0[3]); \
    FMA_F32X2(Q0[4], xs0, _wc.x, Q0[4]); \
    FMA_F32X2(Q0[5], xs0, _wc.y, Q0[5]); \
    FMA_F32X2(Q0[6], xs0, _wd.x, Q0[6]); \
    FMA_F32X2(Q0[7], xs0, _wd.y, Q0[7]); \
    FMA_F32X2(Q1[0], xs1, _wa.x, Q1[0]); \
    FMA_F32X2(Q1[1], xs1, _wa.y, Q1[1]); \
    FMA_F32X2(Q1[2], xs1, _wb.x, Q1[2]); \
    FMA_F32X2(Q1[3], xs1, _wb.y, Q1[3]); \
    FMA_F32X2(Q1[4], xs1, _wc.x, Q1[4]); \
    FMA_F32X2(Q1[5], xs1, _wc.y, Q1[5]); \
    FMA_F32X2(Q1[6], xs1, _wd.x, Q1[6]); \
    FMA_F32X2(Q1[7], xs1, _wd.y, Q1[7]); \
} while (0)

// ======================= K1a: occ layer 0 (32 -> 64 sp) ====================
__global__ __launch_bounds__(TPB, 4)
void k1a_occ0(const float* __restrict__ embedded,
              const float* __restrict__ occ_W0,
              const float* __restrict__ occ_b0)
{
    __shared__ float sw[32*64 + 64];
    const int tid = threadIdx.x;
    for (int t = tid; t < 32*64; t += TPB) sw[t] = occ_W0[t];
    if (tid < 64) sw[32*64 + tid] = occ_b0[tid];
    __syncthreads();

    const int p0 = blockIdx.x * (2*TPB) + 2*tid;

    float e0[EMB], e1[EMB];
    {
        const float4* q0 = (const float4*)(embedded + (size_t)p0 * EMB);
        #pragma unroll
        for (int q = 0; q < EMB/4; q++) {
            float4 v0 = q0[q], v1 = q0[q + EMB/4];
            e0[4*q]=v0.x; e0[4*q+1]=v0.y; e0[4*q+2]=v0.z; e0[4*q+3]=v0.w;
            e1[4*q]=v1.x; e1[4*q+1]=v1.y; e1[4*q+2]=v1.z; e1[4*q+3]=v1.w;
        }
    }

    #pragma unroll
    for (int q = 0; q < 4; q++) {
        u64t Q0[8], Q1[8];
        const u64t* bp = (const u64t*)(sw + 32*64) + q*8;
        #pragma unroll
        for (int m = 0; m < 8; m++) { Q0[m] = bp[m]; Q1[m] = bp[m]; }

        #pragma unroll 8
        for (int k = 0; k < EMB; k++) {
            u64t xs0, xs1;
            PACK_SPLAT(xs0, e0[k]);
            PACK_SPLAT(xs1, e1[k]);
            QSTEP(Q0, Q1, xs0, xs1, sw + k*64 + q*16);
        }

        #pragma unroll
        for (int m = 0; m < 8; m++) {
            unsigned l0, h0, l1, h1;
            UNPACK_F32X2U(l0, h0, Q0[m]);
            UNPACK_F32X2U(l1, h1, Q1[m]);
            float2 va = make_float2(sp_fast(__uint_as_float(l0)), sp_fast(__uint_as_float(l1)));
            float2 vb = make_float2(sp_fast(__uint_as_float(h0)), sp_fast(__uint_as_float(h1)));
            *(float2*)(g_a + (size_t)(q*16 + 2*m)     * NPTS + p0) = va;
            *(float2*)(g_a + (size_t)(q*16 + 2*m + 1) * NPTS + p0) = vb;
        }
    }
}

// ========== K1b: occ L1 (64->64 sp) fused occ L2 (64->16 lin) + dir copy ===
__global__ __launch_bounds__(TPB, 4)
void k1b_occ12(const float* __restrict__ embedded_dir,
               const float* __restrict__ occ_W1, const float* __restrict__ occ_b1,
               const float* __restrict__ occ_W2, const float* __restrict__ occ_b2,
               float* __restrict__ out)
{
    __shared__ float sw[64*64 + 64*16 + 64 + 16];
    const int W2o = 64*64, B1o = W2o + 64*16, B2o = B1o + 64;
    const int tid = threadIdx.x;
    for (int t = tid; t < 64*64; t += TPB) sw[t] = occ_W1[t];
    for (int t = tid; t < 64*16; t += TPB) sw[W2o + t] = occ_W2[t];
    if (tid < 64) sw[B1o + tid] = occ_b1[tid];
    if (tid >= 64 && tid < 80) sw[B2o + tid - 64] = occ_b2[tid - 64];
    __syncthreads();

    const int p0 = blockIdx.x * (2*TPB) + 2*tid;

    u64t C0[8], C1[8];
    {
        const u64t* bp = (const u64t*)(sw + B2o);
        #pragma unroll
        for (int m = 0; m < 8; m++) { C0[m] = bp[m]; C1[m] = bp[m]; }
    }

    #pragma unroll
    for (int q = 0; q < 4; q++) {
        u64t Q0[8], Q1[8];
        const u64t* bp = (const u64t*)(sw + B1o) + q*8;
        #pragma unroll
        for (int m = 0; m < 8; m++) { Q0[m] = bp[m]; Q1[m] = bp[m]; }

        #pragma unroll 8
        for (int k = 0; k < 64; k++) {
            float2 xv = *(const float2*)(g_a + (size_t)k * NPTS + p0);
            u64t xs0, xs1;
            PACK_SPLAT(xs0, xv.x);
            PACK_SPLAT(xs1, xv.y);
            QSTEP(Q0, Q1, xs0, xs1, sw + k*64 + q*16);
        }

        float h0[16], h1[16];
        #pragma unroll
        for (int m = 0; m < 8; m++) {
            unsigned lo, hi;
            UNPACK_F32X2U(lo, hi, Q0[m]);
            h0[2*m]   = sp_fast(__uint_as_float(lo));
            h0[2*m+1] = sp_fast(__uint_as_float(hi));
            UNPACK_F32X2U(lo, hi, Q1[m]);
            h1[2*m]   = sp_fast(__uint_as_float(lo));
            h1[2*m+1] = sp_fast(__uint_as_float(hi));
        }

        #pragma unroll
        for (int kk = 0; kk < 16; kk++) {
            const int kq = q*16 + kk;
            u64t xs0, xs1;
            PACK_SPLAT(xs0, h0[kk]);
            PACK_SPLAT(xs1, h1[kk]);
            QSTEP(C0, C1, xs0, xs1, sw + W2o + kq*16);
        }
    }

    float hid0[16], hid1[16];
    #pragma unroll
    for (int m = 0; m < 8; m++) {
        unsigned lo, hi;
        UNPACK_F32X2U(lo, hi, C0[m]);
        hid0[2*m]   = __uint_as_float(lo);
        hid0[2*m+1] = __uint_as_float(hi);
        UNPACK_F32X2U(lo, hi, C1[m]);
        hid1[2*m]   = __uint_as_float(lo);
        hid1[2*m+1] = __uint_as_float(hi);
    }

    const float occ0 = 1.0f - __expf(-sp_fast(hid0[0]));
    const float occ1 = 1.0f - __expf(-sp_fast(hid1[0]));
    out[(size_t)NPTS*4 + p0]     = occ0;
    out[(size_t)NPTS*4 + p0 + 1] = occ1;

    #pragma unroll
    for (int n = 1; n < 16; n++)
        *(float2*)(g_x2 + (size_t)(DIRD + n - 1) * NPTS + p0) =
            make_float2(hid0[n], hid1[n]);

    // dir copy into transposed x2 rows 0..26
    {
        const float* d0 = embedded_dir + (size_t)p0 * DIRD;
        const float* d1 = d0 + DIRD;
        #pragma unroll
        for (int k = 0; k < DIRD; k++)
            *(float2*)(g_x2 + (size_t)k * NPTS + p0) = make_float2(d0[k], d1[k]);
    }
}

// ================= K2: rgb layer 0 (74 -> 64 sp, latent-folded) ============
__global__ __launch_bounds__(TPB, 4)
void k2_rgb0(const float* __restrict__ embedded,
             const float* __restrict__ rgb_W0, const float* __restrict__ rgb_b0,
             const float* __restrict__ rgb_latent,
             const int*   __restrict__ latent_index)
{
    __shared__ float sw[74*64 + 64];
    const int LATBo = 74*64;
    const int tid = threadIdx.x;
    for (int t = tid; t < 74*64; t += TPB) sw[t] = rgb_W0[t];
    if (tid >= 64) {
        const int j = tid - 64;
        const int li = *latent_index;
        const float* lrow = rgb_latent + li * LAT;
        float acc = rgb_b0[j];
        #pragma unroll 8
        for (int l = 0; l < LAT; l++)
            acc = fmaf(lrow[l], rgb_W0[(RGBK + l) * 64 + j], acc);
        sw[LATBo + j] = acc;
    }
    __syncthreads();

    const int p0 = blockIdx.x * (2*TPB) + 2*tid;

    float e0[EMB], e1[EMB];
    {
        const float4* q0 = (const float4*)(embedded + (size_t)p0 * EMB);
        #pragma unroll
        for (int q = 0; q < EMB/4; q++) {
            float4 v0 = q0[q], v1 = q0[q + EMB/4];
            e0[4*q]=v0.x; e0[4*q+1]=v0.y; e0[4*q+2]=v0.z; e0[4*q+3]=v0.w;
            e1[4*q]=v1.x; e1[4*q+1]=v1.y; e1[4*q+2]=v1.z; e1[4*q+3]=v1.w;
        }
    }

    #pragma unroll
    for (int q = 0; q < 4; q++) {
        u64t Q0[8], Q1[8];
        const u64t* bp = (const u64t*)(sw + LATBo) + q*8;
        #pragma unroll
        for (int m = 0; m < 8; m++) { Q0[m] = bp[m]; Q1[m] = bp[m]; }

        #pragma unroll 8
        for (int k = 0; k < EMB; k++) {
            u64t xs0, xs1;
            PACK_SPLAT(xs0, e0[k]);
            PACK_SPLAT(xs1, e1[k]);
            QSTEP(Q0, Q1, xs0, xs1, sw + k*64 + q*16);
        }
        #pragma unroll 7
        for (int kx = 0; kx < X2K; kx++) {
            float2 xv = *(const float2*)(g_x2 + (size_t)kx * NPTS + p0);
            u64t xs0, xs1;
            PACK_SPLAT(xs0, xv.x);
            PACK_SPLAT(xs1, xv.y);
            QSTEP(Q0, Q1, xs0, xs1, sw + (EMB + kx)*64 + q*16);
        }

        #pragma unroll
        for (int m = 0; m < 8; m++) {
            unsigned l0, h0, l1, h1;
            UNPACK_F32X2U(l0, h0, Q0[m]);
            UNPACK_F32X2U(l1, h1, Q1[m]);
            float2 va = make_float2(sp_fast(__uint_as_float(l0)), sp_fast(__uint_as_float(l1)));
            float2 vb = make_float2(sp_fast(__uint_as_float(h0)), sp_fast(__uint_as_float(h1)));
            *(float2*)(g_r + (size_t)(q*16 + 2*m)     * NPTS + p0) = va;
            *(float2*)(g_r + (size_t)(q*16 + 2*m + 1) * NPTS + p0) = vb;
        }
    }
}

// ======= K3: rgb L1 (64->64 sp) fused rgb L2 (64->3 sigmoid) + output ======
__global__ __launch_bounds__(TPB, 4)
void k3_rgb12(const float* __restrict__ rgb_W1, const float* __restrict__ rgb_b1,
              const float* __restrict__ rgb_W2, const float* __restrict__ rgb_b2,
              float* __restrict__ out)
{
    __shared__ float sw[64*64 + 64*4 + 64 + 4];
    const int W2o = 64*64, B1o = W2o + 64*4, B2o = B1o + 64;
    const int tid = threadIdx.x;
    for (int t = tid; t < 64*64; t += TPB) sw[t] = rgb_W1[t];
    for (int t = tid; t < 64*3; t += TPB) {
        int k = t / 3, j = t - 3*k;
        sw[W2o + k*4 + j] = rgb_W2[t];
    }
    for (int t = tid; t < 64; t += TPB) sw[W2o + t*4 + 3] = 0.0f;
    if (tid < 64) sw[B1o + tid] = rgb_b1[tid];
    if (tid >= 64 && tid < 67) sw[B2o + tid - 64] = rgb_b2[tid - 64];
    if (tid == 67) sw[B2o + 3] = 0.0f;
    __syncthreads();

    const int p0 = blockIdx.x * (2*TPB) + 2*tid;

    float c00 = sw[B2o+0], c01 = sw[B2o+1], c02 = sw[B2o+2];
    float c10 = c00, c11 = c01, c12 = c02;

    #pragma unroll
    for (int q = 0; q < 4; q++) {
        u64t Q0[8], Q1[8];
        const u64t* bp = (const u64t*)(sw + B1o) + q*8;
        #pragma unroll
        for (int m = 0; m < 8; m++) { Q0[m] = bp[m]; Q1[m] = bp[m]; }

        #pragma unroll 8
        for (int k = 0; k < 64; k++) {
            float2 xv = *(const float2*)(g_r + (size_t)k * NPTS + p0);
            u64t xs0, xs1;
            PACK_SPLAT(xs0, xv.x);
            PACK_SPLAT(xs1, xv.y);
            QSTEP(Q0, Q1, xs0, xs1, sw + k*64 + q*16);
        }

        #pragma unroll
        for (int m = 0; m < 8; m++) {
            unsigned lo, hi;
            UNPACK_F32X2U(lo, hi, Q0[m]);
            float ha = sp_fast(__uint_as_float(lo));
            float hb = sp_fast(__uint_as_float(hi));
            UNPACK_F32X2U(lo, hi, Q1[m]);
            float hc = sp_fast(__uint_as_float(lo));
            float hd = sp_fast(__uint_as_float(hi));
            const int kq = q*16 + 2*m;
            float4 wA = *(const float4*)(sw + W2o + kq*4);
            float4 wB = *(const float4*)(sw + W2o + (kq+1)*4);
            c00 = fmaf(ha, wA.x, c00); c01 = fmaf(ha, wA.y, c01); c02 = fmaf(ha, wA.z, c02);
            c10 = fmaf(hc, wA.x, c10); c11 = fmaf(hc, wA.y, c11); c12 = fmaf(hc, wA.z, c12);
            c00 = fmaf(hb, wB.x, c00); c01 = fmaf(hb, wB.y, c01); c02 = fmaf(hb, wB.z, c02);
            c10 = fmaf(hd, wB.x, c10); c11 = fmaf(hd, wB.y, c11); c12 = fmaf(hd, wB.z, c12);
        }
    }

    const float o0 = out[(size_t)NPTS*4 + p0];
    const float o1 = out[(size_t)NPTS*4 + p0 + 1];
    float4* o4 = (float4*)out;
    o4[p0]     = make_float4(sigmoid_fast(c00), sigmoid_fast(c01), sigmoid_fast(c02), o0);
    o4[p0 + 1] = make_float4(sigmoid_fast(c10), sigmoid_fast(c11), sigmoid_fast(c12), o1);
}

extern "C" void kernel_launch(void* const* d_in, const int* in_sizes, int n_in,
                              void* d_out, int out_size) {
    const float* embedded     = (const float*)d_in[0];
    const float* embedded_dir = (const float*)d_in[1];
    const float* occ_W0 = (const float*)d_in[2];
    const float* occ_b0 = (const float*)d_in[3];
    const float* occ_W1 = (const float*)d_in[4];
    const float* occ_b1 = (const float*)d_in[5];
    const float* occ_W2 = (const float*)d_in[6];
    const float* occ_b2 = (const float*)d_in[7];
    const float* rgb_W0 = (const float*)d_in[8];
    const float* rgb_b0 = (const float*)d_in[9];
    const float* rgb_W1 = (const float*)d_in[10];
    const float* rgb_b1 = (const float*)d_in[11];
    const float* rgb_W2 = (const float*)d_in[12];
    const float* rgb_b2 = (const float*)d_in[13];
    const float* rgb_latent = (const float*)d_in[14];
    const int*   latent_index = (const int*)d_in[15];
    float* out = (float*)d_out;

    const int grid = NPTS / (2 * TPB);   // 2048
    k1a_occ0 <<<grid, TPB>>>(embedded, occ_W0, occ_b0);
    k1b_occ12<<<grid, TPB>>>(embedded_dir, occ_W1, occ_b1, occ_W2, occ_b2, out);
    k2_rgb0  <<<grid, TPB>>>(embedded, rgb_W0, rgb_b0, rgb_latent, latent_index);
    k3_rgb12 <<<grid, TPB>>>(rgb_W1, rgb_b1, rgb_W2, rgb_b2, out);
}